// round 14
// baseline (speedup 1.0000x reference)
#include <cuda_runtime.h>
#include <cuda_bf16.h>
#include <cuda_pipeline.h>
#include <mma.h>
#include <math.h>

using namespace nvcuda;

constexpr int TT = 180;
constexpr int BB = 512;
constexpr int II = 108;
constexpr int HH = 1024;
constexpr int VV = 108;
constexpr int G4 = 4096;
constexpr int NB = 128;
constexpr int NTHR = 256;
constexpr int K1P = 1152;
constexpr int K2P = 2048;
constexpr int PA = 72;
constexpr int PO = 132;
constexpr int BUF = 128*PA;
constexpr int DSM = 3*4*BUF*2;

typedef __nv_bfloat16 bf;

__device__ bf g_W1h[(long)G4*K1P], g_W1l[(long)G4*K1P];
__device__ bf g_W2h[(long)G4*K2P], g_W2l[(long)G4*K2P];
__device__ bf g_Wmh[(long)HH*HH], g_Wml[(long)HH*HH];
__device__ bf g_xh[(long)TT*BB*128], g_xl[(long)TT*BB*128];
__device__ bf g_h1h[2][BB*HH], g_h1l[2][BB*HH];
__device__ bf g_h2h[2][BB*HH], g_h2l[2][BB*HH];
__device__ bf g_c1h[BB*HH], g_c1l[BB*HH];
__device__ bf g_msh[BB*HH], g_msl[BB*HH];
__device__ float g_c1[BB*HH], g_c2[BB*HH];
__device__ float g_bias1[G4], g_bias2[G4];
__device__ float g_WfinT[HH*128];
__device__ unsigned g_arrive;
__device__ volatile unsigned g_release;

__device__ __forceinline__ void split_bf(float v, bf& hi, bf& lo) {
    hi = __float2bfloat16(v);
    lo = __float2bfloat16(v - __bfloat162float(hi));
}

__device__ __forceinline__ float sigmf(float x) {
    return 1.f / (1.f + expf(-x));
}

__device__ __forceinline__ int prow_n(int p) {
    return ((p >> 5) & 3)*HH + (p >> 7)*32 + (p & 31);
}

__global__ void prep(const float* __restrict__ x,
                     const float* __restrict__ Wi1,
                     const float* __restrict__ Wh1,
                     const float* __restrict__ bi1,
                     const float* __restrict__ bh1,
                     const float* __restrict__ Wm,
                     const float* __restrict__ Wi2,
                     const float* __restrict__ Wh2,
                     const float* __restrict__ bi2,
                     const float* __restrict__ bh2,
                     const float* __restrict__ Wf) {
    if (blockIdx.x == 0 && threadIdx.x == 0) {
        g_arrive = 0u;
        g_release = 0u;
    }
    const long NW1 = (long)G4*K1P;
    const long NW2 = (long)G4*K2P;
    const long NWM = (long)HH*HH;
    const long NX = (long)TT*BB*128;
    const long NH = (long)BB*HH;
    const long total = NW1 + NW2 + NWM + NX + 6*NH + 2*G4 + (long)HH*128;
    long idx = blockIdx.x*(long)blockDim.x + threadIdx.x;
    const long stride = (long)gridDim.x*blockDim.x;
    for (; idx < total; idx += stride) {
        long i = idx;
        if (i < NW1) {
            int p = (int)(i / K1P);
            int k = (int)(i - (long)p*K1P);
            int n = prow_n(p);
            float v = 0.f;
            if (k < HH) v = Wh1[(long)n*HH + k];
            else if (k - HH < II) v = Wi1[(long)n*II + (k - HH)];
            bf hi, lo;
            split_bf(v, hi, lo);
            g_W1h[i] = hi;
            g_W1l[i] = lo;
            continue;
        }
        i -= NW1;
        if (i < NW2) {
            int p = (int)(i >> 11);
            int k = (int)(i & 2047);
            int n = prow_n(p);
            float v;
            if (k < HH) v = Wi2[(long)n*HH + k];
            else v = Wh2[(long)n*HH + (k - HH)];
            bf hi, lo;
            split_bf(v, hi, lo);
            g_W2h[i] = hi;
            g_W2l[i] = lo;
            continue;
        }
        i -= NW2;
        if (i < NWM) {
            float v = Wm[i];
            bf hi, lo;
            split_bf(v, hi, lo);
            g_Wmh[i] = hi;
            g_Wml[i] = lo;
            continue;
        }
        i -= NWM;
        if (i < NX) {
            int t = (int)(i / (BB*128));
            int r = (int)(i - (long)t*BB*128);
            int b = r >> 7;
            int kx = r & 127;
            float v = 0.f;
            if (kx < II) v = x[((long)t*BB + b)*II + kx];
            bf hi, lo;
            split_bf(v, hi, lo);
            g_xh[i] = hi;
            g_xl[i] = lo;
            continue;
        }
        i -= NX;
        if (i < 4*NH) {
            long a = i / NH;
            long off = i - a*NH;
            bf z = __float2bfloat16(0.f);
            if (a == 0) g_h1h[0][off] = z;
            else if (a == 1) g_h1l[0][off] = z;
            else if (a == 2) g_h2h[0][off] = z;
            else g_h2l[0][off] = z;
            continue;
        }
        i -= 4*NH;
        if (i < NH) { g_c1[i] = 0.f; continue; }
        i -= NH;
        if (i < NH) { g_c2[i] = 0.f; continue; }
        i -= NH;
        if (i < G4) {
            int n = prow_n((int)i);
            g_bias1[i] = bi1[n] + bh1[n];
            continue;
        }
        i -= G4;
        if (i < G4) {
            int n = prow_n((int)i);
            g_bias2[i] = bi2[n] + bh2[n];
            continue;
        }
        i -= G4;
        int k = (int)(i >> 7);
        int v = (int)(i & 127);
        g_WfinT[i] = (v < VV) ? Wf[(long)v*HH + k] : 0.f;
    }
}

__device__ __forceinline__ void gsync(unsigned& expected) {
    __syncthreads();
    if (threadIdx.x == 0) {
        __threadfence();
        expected += NB;
        unsigned a = atomicAdd(&g_arrive, 1u) + 1u;
        if (a == expected) g_release = expected;
        else while (g_release < expected) { __nanosleep(64); }
        __threadfence();
    }
    __syncthreads();
}

__device__ void big_phase(const bf* a1h, const bf* a1l, int a1w, int a1c,
                          const bf* a2h, const bf* a2l, int a2w,
                          const bf* wHi, const bf* wLo, int kW, int nch,
                          const float* biasP, float* cst,
                          bf* hOh, bf* hOl, bf* cOh, bf* cOl,
                          int mt, int nt, char* smb) {
    bf* base = (bf*)smb;
    float* sout = (float*)smb;
    const int tid = threadIdx.x;
    const int wid = tid >> 5;
    const int wr = wid & 3;
    const int wc = wid >> 2;
    const int m0 = mt*128;
    const int n0 = nt*128;

    wmma::fragment<wmma::accumulator, 16, 16, 16, float> acc[2][4];
    for (int i = 0; i < 2; i++)
        for (int j = 0; j < 4; j++)
            wmma::fill_fragment(acc[i][j], 0.f);

    auto pre = [&](int c) {
        const int s = c % 3;
        const bf* ah;
        const bf* al;
        int aw, col;
        if (c < a1c) {
            ah = a1h; al = a1l; aw = a1w; col = c*64;
        } else {
            ah = a2h; al = a2l; aw = a2w; col = (c - a1c)*64;
        }
        bf* dAh = base + (s*4 + 0)*BUF;
        bf* dAl = base + (s*4 + 1)*BUF;
        bf* dWh = base + (s*4 + 2)*BUF;
        bf* dWl = base + (s*4 + 3)*BUF;
        for (int i = tid; i < 1024; i += NTHR) {
            int r = i >> 3;
            int cg = (i & 7)*8;
            int so = r*PA + cg;
            __pipeline_memcpy_async(dAh + so, ah + (size_t)(m0 + r)*aw + col + cg, 16);
            __pipeline_memcpy_async(dAl + so, al + (size_t)(m0 + r)*aw + col + cg, 16);
            __pipeline_memcpy_async(dWh + so, wHi + (size_t)(n0 + r)*kW + c*64 + cg, 16);
            __pipeline_memcpy_async(dWl + so, wLo + (size_t)(n0 + r)*kW + c*64 + cg, 16);
        }
        __pipeline_commit();
    };

    pre(0);
    pre(1);
    for (int c = 0; c < nch; c++) {
        if (c + 1 < nch) __pipeline_wait_prior(1);
        else __pipeline_wait_prior(0);
        __syncthreads();
        if (c + 2 < nch) pre(c + 2);
        const int s = c % 3;
        bf* cAh = base + (s*4 + 0)*BUF;
        bf* cAl = base + (s*4 + 1)*BUF;
        bf* cWh = base + (s*4 + 2)*BUF;
        bf* cWl = base + (s*4 + 3)*BUF;
        for (int ks = 0; ks < 4; ks++) {
            wmma::fragment<wmma::matrix_a, 16, 16, 16, bf, wmma::row_major> fah[2];
            wmma::fragment<wmma::matrix_a, 16, 16, 16, bf, wmma::row_major> fal[2];
            for (int i = 0; i < 2; i++) {
                const bf* pa = cAh + (wr*32 + i*16)*PA + ks*16;
                const bf* pb = cAl + (wr*32 + i*16)*PA + ks*16;
                wmma::load_matrix_sync(fah[i], pa, PA);
                wmma::load_matrix_sync(fal[i], pb, PA);
            }
            for (int j = 0; j < 4; j++) {
                wmma::fragment<wmma::matrix_b, 16, 16, 16, bf, wmma::col_major> fwh;
                wmma::fragment<wmma::matrix_b, 16, 16, 16, bf, wmma::col_major> fwl;
                const bf* ph = cWh + (wc*64 + j*16)*PA + ks*16;
                const bf* pl = cWl + (wc*64 + j*16)*PA + ks*16;
                wmma::load_matrix_sync(fwh, ph, PA);
                wmma::load_matrix_sync(fwl, pl, PA);
                for (int i = 0; i < 2; i++) {
                    wmma::mma_sync(acc[i][j], fah[i], fwh, acc[i][j]);
                    wmma::mma_sync(acc[i][j], fal[i], fwh, acc[i][j]);
                    wmma::mma_sync(acc[i][j], fah[i], fwl, acc[i][j]);
                }
            }
        }
    }
    __syncthreads();

    for (int i = 0; i < 2; i++)
        for (int j = 0; j < 4; j++) {
            float* po = sout + (wr*32 + i*16)*PO + wc*64 + j*16;
            wmma::store_matrix_sync(po, acc[i][j], PO, wmma::mem_row_major);
        }
    __syncthreads();

    for (int e = tid; e < 4096; e += NTHR) {
        int ml = e >> 5;
        int jin = e & 31;
        const float* bse = sout + ml*PO + jin;
        float ig = sigmf(bse[0] + biasP[n0 + jin]);
        float fg = sigmf(bse[32] + biasP[n0 + 32 + jin]);
        float gg = tanhf(bse[64] + biasP[n0 + 64 + jin]);
        float og = sigmf(bse[96] + biasP[n0 + 96 + jin]);
        int j = nt*32 + jin;
        size_t ci = (size_t)(m0 + ml)*HH + j;
        float cn = fg*cst[ci] + ig*gg;
        cst[ci] = cn;
        float hn = og*tanhf(cn);
        bf ha, hb;
        split_bf(hn, ha, hb);
        hOh[ci] = ha;
        hOl[ci] = hb;
        if (cOh != 0) {
            bf ca, cb;
            split_bf(cn, ca, cb);
            cOh[ci] = ca;
            cOl[ci] = cb;
        }
    }
    __syncthreads();
}

__device__ void mid_phase(const float* bm, int bid, char* smb) {
    bf* base = (bf*)smb;
    float* sout = (float*)smb;
    const int tid = threadIdx.x;
    const int wid = tid >> 5;
    const int wr = wid & 3;
    const int wc = wid >> 2;
    const int m0 = (bid >> 4)*64;
    const int n0 = (bid & 15)*64;
    const int MB = 64*PA;

    wmma::fragment<wmma::accumulator, 16, 16, 16, float> acc[2];
    wmma::fill_fragment(acc[0], 0.f);
    wmma::fill_fragment(acc[1], 0.f);

    auto pre = [&](int c) {
        const int s = c % 3;
        bf* dAh = base + (s*4 + 0)*MB;
        bf* dAl = base + (s*4 + 1)*MB;
        bf* dWh = base + (s*4 + 2)*MB;
        bf* dWl = base + (s*4 + 3)*MB;
        for (int i = tid; i < 512; i += NTHR) {
            int r = i >> 3;
            int cg = (i & 7)*8;
            int so = r*PA + cg;
            size_t ga = (size_t)(m0 + r)*HH + c*64 + cg;
            size_t gw = (size_t)(n0 + r)*HH + c*64 + cg;
            __pipeline_memcpy_async(dAh + so, g_c1h + ga, 16);
            __pipeline_memcpy_async(dAl + so, g_c1l + ga, 16);
            __pipeline_memcpy_async(dWh + so, g_Wmh + gw, 16);
            __pipeline_memcpy_async(dWl + so, g_Wml + gw, 16);
        }
        __pipeline_commit();
    };

    pre(0);
    pre(1);
    for (int c = 0; c < 16; c++) {
        if (c + 1 < 16) __pipeline_wait_prior(1);
        else __pipeline_wait_prior(0);
        __syncthreads();
        if (c + 2 < 16) pre(c + 2);
        const int s = c % 3;
        bf* cAh = base + (s*4 + 0)*MB;
        bf* cAl = base + (s*4 + 1)*MB;
        bf* cWh = base + (s*4 + 2)*MB;
        bf* cWl = base + (s*4 + 3)*MB;
        for (int ks = 0; ks < 4; ks++) {
            wmma::fragment<wmma::matrix_a, 16, 16, 16, bf, wmma::row_major> fah;
            wmma::fragment<wmma::matrix_a, 16, 16, 16, bf, wmma::row_major> fal;
            wmma::load_matrix_sync(fah, cAh + (wr*16)*PA + ks*16, PA);
            wmma::load_matrix_sync(fal, cAl + (wr*16)*PA + ks*16, PA);
            for (int j = 0; j < 2; j++) {
                wmma::fragment<wmma::matrix_b, 16, 16, 16, bf, wmma::col_major> fwh;
                wmma::fragment<wmma::matrix_b, 16, 16, 16, bf, wmma::col_major> fwl;
                const bf* ph = cWh + (wc*32 + j*16)*PA + ks*16;
                const bf* pl = cWl + (wc*32 + j*16)*PA + ks*16;
                wmma::load_matrix_sync(fwh, ph, PA);
                wmma::load_matrix_sync(fwl, pl, PA);
                wmma::mma_sync(acc[j], fah, fwh, acc[j]);
                wmma::mma_sync(acc[j], fal, fwh, acc[j]);
                wmma::mma_sync(acc[j], fah, fwl, acc[j]);
            }
        }
    }
    __syncthreads();

    for (int j = 0; j < 2; j++) {
        float* po = sout + (wr*16)*68 + wc*32 + j*16;
        wmma::store_matrix_sync(po, acc[j], 68, wmma::mem_row_major);
    }
    __syncthreads();

    for (int e = tid; e < 4096; e += NTHR) {
        int ml = e >> 6;
        int nl = e & 63;
        float v = sout[ml*68 + nl] + bm[n0 + nl];
        bf ha, hb;
        split_bf(v, ha, hb);
        size_t di = (size_t)(m0 + ml)*HH + n0 + nl;
        g_msh[di] = ha;
        g_msl[di] = hb;
    }
    __syncthreads();
}

__device__ void fin_phase(const float* __restrict__ bfin, float* outT,
                          int bid, char* smb) {
    float* cs = (float*)smb;
    float* sh = (float*)(smb + 16384);
    float* red = (float*)(smb + 18432);
    const int b0 = bid*4;
    const int tid = threadIdx.x;
    for (int idx = tid; idx < 4*HH; idx += NTHR) {
        int rr = idx >> 10;
        int kk = idx & 1023;
        cs[idx] = __ldcg(&g_c2[(size_t)(b0 + rr)*HH + kk]);
    }
    __syncthreads();
    const int v = tid & 127;
    const int rh = (tid >> 7)*2;
    float a0 = 0.f;
    float a1 = 0.f;
    for (int k = 0; k < HH; k += 4) {
        float w0 = g_WfinT[(k + 0)*128 + v];
        float w1 = g_WfinT[(k + 1)*128 + v];
        float w2 = g_WfinT[(k + 2)*128 + v];
        float w3 = g_WfinT[(k + 3)*128 + v];
        float4 c0 = *(const float4*)(cs + rh*1024 + k);
        float4 c1 = *(const float4*)(cs + rh*1024 + 1024 + k);
        a0 += c0.x*w0 + c0.y*w1 + c0.z*w2 + c0.w*w3;
        a1 += c1.x*w0 + c1.y*w1 + c1.z*w2 + c1.w*w3;
    }
    float bb = (v < VV) ? bfin[v] : 0.f;
    float v0 = (v < VV) ? (a0 + bb) : -1e30f;
    float v1 = (v < VV) ? (a1 + bb) : -1e30f;
    sh[rh*128 + v] = v0;
    sh[rh*128 + 128 + v] = v1;
    __syncthreads();
    if (tid < 4) {
        float mx = -1e30f;
        for (int j = 0; j < VV; j++) mx = fmaxf(mx, sh[tid*128 + j]);
        float s = 0.f;
        for (int j = 0; j < VV; j++) s += expf(sh[tid*128 + j] - mx);
        red[tid] = mx;
        red[4 + tid] = logf(s);
    }
    __syncthreads();
    if (v < VV) {
        float o0 = v0 - red[rh] - red[4 + rh];
        float o1 = v1 - red[rh + 1] - red[4 + rh + 1];
        outT[(size_t)(b0 + rh)*VV + v] = o0;
        outT[(size_t)(b0 + rh + 1)*VV + v] = o1;
    }
    __syncthreads();
}

__global__ void __launch_bounds__(NTHR)
lstm_tc(const float* __restrict__ bm, const float* __restrict__ bfin,
        float* __restrict__ out) {
    extern __shared__ char smb[];
    const int bid = blockIdx.x;
    unsigned expected = 0;
    const int mt = bid >> 5;
    const int nt = bid & 31;

    for (int t = 0; t < TT; t++) {
        const int cur = t & 1;
        const int nxt = cur ^ 1;
        big_phase(g_h1h[cur], g_h1l[cur], HH, 16,
                  g_xh + (long)t*BB*128, g_xl + (long)t*BB*128, 128,
                  g_W1h, g_W1l, K1P, 18,
                  g_bias1, g_c1, g_h1h[nxt], g_h1l[nxt],
                  g_c1h, g_c1l, mt, nt, smb);
        gsync(expected);
        mid_phase(bm, bid, smb);
        gsync(expected);
        big_phase(g_msh, g_msl, HH, 16,
                  g_h2h[cur], g_h2l[cur], HH,
                  g_W2h, g_W2l, K2P, 32,
                  g_bias2, g_c2, g_h2h[nxt], g_h2l[nxt],
                  (bf*)0, (bf*)0, mt, nt, smb);
        gsync(expected);
        fin_phase(bfin, out + (size_t)t*BB*VV, bid, smb);
    }
}

extern "C" void kernel_launch(void* const* d_in, const int* in_sizes,
                              int n_in, void* d_out, int out_size) {
    const float* x = (const float*)d_in[0];
    const float* Wi1 = (const float*)d_in[1];
    const float* Wh1 = (const float*)d_in[2];
    const float* bi1 = (const float*)d_in[3];
    const float* bh1 = (const float*)d_in[4];
    const float* Wm = (const float*)d_in[5];
    const float* bm = (const float*)d_in[6];
    const float* Wi2 = (const float*)d_in[7];
    const float* Wh2 = (const float*)d_in[8];
    const float* bi2 = (const float*)d_in[9];
    const float* bh2 = (const float*)d_in[10];
    const float* Wf = (const float*)d_in[11];
    const float* bfin = (const float*)d_in[12];
    float* out = (float*)d_out;

    cudaFuncSetAttribute(lstm_tc,
                         cudaFuncAttributeMaxDynamicSharedMemorySize, DSM);
    prep<<<4096, 256>>>(x, Wi1, Wh1, bi1, bh1, Wm,
                        Wi2, Wh2, bi2, bh2, Wf);
    lstm_tc<<<NB, NTHR, DSM>>>(bm, bfin, out);
}

// round 15
// speedup vs baseline: 1.0192x; 1.0192x over previous
#include <cuda_runtime.h>
#include <cuda_bf16.h>
#include <cuda_pipeline.h>
#include <mma.h>
#include <math.h>

using namespace nvcuda;

constexpr int TT = 180;
constexpr int BB = 512;
constexpr int II = 108;
constexpr int HH = 1024;
constexpr int VV = 108;
constexpr int G4 = 4096;
constexpr int NB = 128;
constexpr int NTHR = 512;
constexpr int K1P = 1152;
constexpr int K2P = 2048;
constexpr int PA = 72;
constexpr int PO = 132;
constexpr int BUF = 128*PA;
constexpr int DSM = 3*4*BUF*2;

typedef __nv_bfloat16 bf;

__device__ bf g_W1h[(long)G4*K1P], g_W1l[(long)G4*K1P];
__device__ bf g_W2h[(long)G4*K2P], g_W2l[(long)G4*K2P];
__device__ bf g_Wmh[(long)HH*HH], g_Wml[(long)HH*HH];
__device__ bf g_xh[(long)TT*BB*128], g_xl[(long)TT*BB*128];
__device__ bf g_h1h[2][BB*HH], g_h1l[2][BB*HH];
__device__ bf g_h2h[2][BB*HH], g_h2l[2][BB*HH];
__device__ bf g_c1h[BB*HH], g_c1l[BB*HH];
__device__ bf g_msh[BB*HH], g_msl[BB*HH];
__device__ float g_c1[BB*HH], g_c2[BB*HH];
__device__ float g_bias1[G4], g_bias2[G4];
__device__ float g_WfinT[HH*128];
__device__ unsigned g_arrive;
__device__ volatile unsigned g_release;

__device__ __forceinline__ void split_bf(float v, bf& hi, bf& lo) {
    hi = __float2bfloat16(v);
    lo = __float2bfloat16(v - __bfloat162float(hi));
}

__device__ __forceinline__ float sigmf(float x) {
    return 1.f / (1.f + expf(-x));
}

__device__ __forceinline__ int prow_n(int p) {
    return ((p >> 5) & 3)*HH + (p >> 7)*32 + (p & 31);
}

__global__ void prep(const float* __restrict__ x,
                     const float* __restrict__ Wi1,
                     const float* __restrict__ Wh1,
                     const float* __restrict__ bi1,
                     const float* __restrict__ bh1,
                     const float* __restrict__ Wm,
                     const float* __restrict__ Wi2,
                     const float* __restrict__ Wh2,
                     const float* __restrict__ bi2,
                     const float* __restrict__ bh2,
                     const float* __restrict__ Wf) {
    if (blockIdx.x == 0 && threadIdx.x == 0) {
        g_arrive = 0u;
        g_release = 0u;
    }
    const long NW1 = (long)G4*K1P;
    const long NW2 = (long)G4*K2P;
    const long NWM = (long)HH*HH;
    const long NX = (long)TT*BB*128;
    const long NH = (long)BB*HH;
    const long total = NW1 + NW2 + NWM + NX + 6*NH + 2*G4 + (long)HH*128;
    long idx = blockIdx.x*(long)blockDim.x + threadIdx.x;
    const long stride = (long)gridDim.x*blockDim.x;
    for (; idx < total; idx += stride) {
        long i = idx;
        if (i < NW1) {
            int p = (int)(i / K1P);
            int k = (int)(i - (long)p*K1P);
            int n = prow_n(p);
            float v = 0.f;
            if (k < HH) v = Wh1[(long)n*HH + k];
            else if (k - HH < II) v = Wi1[(long)n*II + (k - HH)];
            bf hi, lo;
            split_bf(v, hi, lo);
            g_W1h[i] = hi;
            g_W1l[i] = lo;
            continue;
        }
        i -= NW1;
        if (i < NW2) {
            int p = (int)(i >> 11);
            int k = (int)(i & 2047);
            int n = prow_n(p);
            float v;
            if (k < HH) v = Wi2[(long)n*HH + k];
            else v = Wh2[(long)n*HH + (k - HH)];
            bf hi, lo;
            split_bf(v, hi, lo);
            g_W2h[i] = hi;
            g_W2l[i] = lo;
            continue;
        }
        i -= NW2;
        if (i < NWM) {
            float v = Wm[i];
            bf hi, lo;
            split_bf(v, hi, lo);
            g_Wmh[i] = hi;
            g_Wml[i] = lo;
            continue;
        }
        i -= NWM;
        if (i < NX) {
            int t = (int)(i / (BB*128));
            int r = (int)(i - (long)t*BB*128);
            int b = r >> 7;
            int kx = r & 127;
            float v = 0.f;
            if (kx < II) v = x[((long)t*BB + b)*II + kx];
            bf hi, lo;
            split_bf(v, hi, lo);
            g_xh[i] = hi;
            g_xl[i] = lo;
            continue;
        }
        i -= NX;
        if (i < 4*NH) {
            long a = i / NH;
            long off = i - a*NH;
            bf z = __float2bfloat16(0.f);
            if (a == 0) g_h1h[0][off] = z;
            else if (a == 1) g_h1l[0][off] = z;
            else if (a == 2) g_h2h[0][off] = z;
            else g_h2l[0][off] = z;
            continue;
        }
        i -= 4*NH;
        if (i < NH) { g_c1[i] = 0.f; continue; }
        i -= NH;
        if (i < NH) { g_c2[i] = 0.f; continue; }
        i -= NH;
        if (i < G4) {
            int n = prow_n((int)i);
            g_bias1[i] = bi1[n] + bh1[n];
            continue;
        }
        i -= G4;
        if (i < G4) {
            int n = prow_n((int)i);
            g_bias2[i] = bi2[n] + bh2[n];
            continue;
        }
        i -= G4;
        int k = (int)(i >> 7);
        int v = (int)(i & 127);
        g_WfinT[i] = (v < VV) ? Wf[(long)v*HH + k] : 0.f;
    }
}

__device__ __forceinline__ void gsync(unsigned& expected) {
    __syncthreads();
    if (threadIdx.x == 0) {
        __threadfence();
        expected += NB;
        unsigned a = atomicAdd(&g_arrive, 1u) + 1u;
        if (a == expected) g_release = expected;
        else while (g_release < expected) { __nanosleep(64); }
        __threadfence();
    }
    __syncthreads();
}

__device__ void big_phase(const bf* a1h, const bf* a1l, int a1w, int a1c,
                          const bf* a2h, const bf* a2l, int a2w,
                          const bf* wHi, const bf* wLo, int kW, int nch,
                          const float* biasP, float* cst,
                          bf* hOh, bf* hOl, bf* cOh, bf* cOl,
                          int mt, int nt, char* smb) {
    bf* base = (bf*)smb;
    float* sout = (float*)smb;
    const int tid = threadIdx.x;
    const int wid = tid >> 5;
    const int wr = wid & 3;
    const int wc = wid >> 2;
    const int m0 = mt*128;
    const int n0 = nt*128;

    wmma::fragment<wmma::accumulator, 16, 16, 16, float> acc[2][2];
    for (int i = 0; i < 2; i++)
        for (int j = 0; j < 2; j++)
            wmma::fill_fragment(acc[i][j], 0.f);

    auto pre = [&](int c) {
        const int s = c % 3;
        const bf* ah;
        const bf* al;
        int aw, col;
        if (c < a1c) {
            ah = a1h; al = a1l; aw = a1w; col = c*64;
        } else {
            ah = a2h; al = a2l; aw = a2w; col = (c - a1c)*64;
        }
        bf* dAh = base + (s*4 + 0)*BUF;
        bf* dAl = base + (s*4 + 1)*BUF;
        bf* dWh = base + (s*4 + 2)*BUF;
        bf* dWl = base + (s*4 + 3)*BUF;
        for (int i = tid; i < 1024; i += NTHR) {
            int r = i >> 3;
            int cg = (i & 7)*8;
            int so = r*PA + cg;
            __pipeline_memcpy_async(dAh + so, ah + (size_t)(m0 + r)*aw + col + cg, 16);
            __pipeline_memcpy_async(dAl + so, al + (size_t)(m0 + r)*aw + col + cg, 16);
            __pipeline_memcpy_async(dWh + so, wHi + (size_t)(n0 + r)*kW + c*64 + cg, 16);
            __pipeline_memcpy_async(dWl + so, wLo + (size_t)(n0 + r)*kW + c*64 + cg, 16);
        }
        __pipeline_commit();
    };

    pre(0);
    pre(1);
    for (int c = 0; c < nch; c++) {
        if (c + 1 < nch) __pipeline_wait_prior(1);
        else __pipeline_wait_prior(0);
        __syncthreads();
        if (c + 2 < nch) pre(c + 2);
        const int s = c % 3;
        bf* cAh = base + (s*4 + 0)*BUF;
        bf* cAl = base + (s*4 + 1)*BUF;
        bf* cWh = base + (s*4 + 2)*BUF;
        bf* cWl = base + (s*4 + 3)*BUF;
        for (int ks = 0; ks < 4; ks++) {
            wmma::fragment<wmma::matrix_a, 16, 16, 16, bf, wmma::row_major> fah[2];
            wmma::fragment<wmma::matrix_a, 16, 16, 16, bf, wmma::row_major> fal[2];
            for (int i = 0; i < 2; i++) {
                const bf* pa = cAh + (wr*32 + i*16)*PA + ks*16;
                const bf* pb = cAl + (wr*32 + i*16)*PA + ks*16;
                wmma::load_matrix_sync(fah[i], pa, PA);
                wmma::load_matrix_sync(fal[i], pb, PA);
            }
            for (int j = 0; j < 2; j++) {
                wmma::fragment<wmma::matrix_b, 16, 16, 16, bf, wmma::col_major> fwh;
                wmma::fragment<wmma::matrix_b, 16, 16, 16, bf, wmma::col_major> fwl;
                const bf* ph = cWh + (wc*32 + j*16)*PA + ks*16;
                const bf* pl = cWl + (wc*32 + j*16)*PA + ks*16;
                wmma::load_matrix_sync(fwh, ph, PA);
                wmma::load_matrix_sync(fwl, pl, PA);
                for (int i = 0; i < 2; i++) {
                    wmma::mma_sync(acc[i][j], fah[i], fwh, acc[i][j]);
                    wmma::mma_sync(acc[i][j], fal[i], fwh, acc[i][j]);
                    wmma::mma_sync(acc[i][j], fah[i], fwl, acc[i][j]);
                }
            }
        }
    }
    __syncthreads();

    for (int i = 0; i < 2; i++)
        for (int j = 0; j < 2; j++) {
            float* po = sout + (wr*32 + i*16)*PO + wc*32 + j*16;
            wmma::store_matrix_sync(po, acc[i][j], PO, wmma::mem_row_major);
        }
    __syncthreads();

    for (int e = tid; e < 4096; e += NTHR) {
        int ml = e >> 5;
        int jin = e & 31;
        const float* bse = sout + ml*PO + jin;
        float ig = sigmf(bse[0] + biasP[n0 + jin]);
        float fg = sigmf(bse[32] + biasP[n0 + 32 + jin]);
        float gg = tanhf(bse[64] + biasP[n0 + 64 + jin]);
        float og = sigmf(bse[96] + biasP[n0 + 96 + jin]);
        int j = nt*32 + jin;
        size_t ci = (size_t)(m0 + ml)*HH + j;
        float cn = fg*cst[ci] + ig*gg;
        cst[ci] = cn;
        float hn = og*tanhf(cn);
        bf ha, hb;
        split_bf(hn, ha, hb);
        hOh[ci] = ha;
        hOl[ci] = hb;
        if (cOh != 0) {
            bf ca, cb;
            split_bf(cn, ca, cb);
            cOh[ci] = ca;
            cOl[ci] = cb;
        }
    }
    __syncthreads();
}

__device__ void mid_phase(const float* bm, int bid, char* smb) {
    bf* base = (bf*)smb;
    float* sout = (float*)smb;
    const int tid = threadIdx.x;
    const int wid = tid >> 5;
    const int wr = wid & 3;
    const int wc = wid >> 2;
    const int m0 = (bid >> 4)*64;
    const int n0 = (bid & 15)*64;
    const int MB = 64*PA;

    wmma::fragment<wmma::accumulator, 16, 16, 16, float> acc;
    wmma::fill_fragment(acc, 0.f);

    auto pre = [&](int c) {
        const int s = c % 3;
        bf* dAh = base + (s*4 + 0)*MB;
        bf* dAl = base + (s*4 + 1)*MB;
        bf* dWh = base + (s*4 + 2)*MB;
        bf* dWl = base + (s*4 + 3)*MB;
        for (int i = tid; i < 512; i += NTHR) {
            int r = i >> 3;
            int cg = (i & 7)*8;
            int so = r*PA + cg;
            size_t ga = (size_t)(m0 + r)*HH + c*64 + cg;
            size_t gw = (size_t)(n0 + r)*HH + c*64 + cg;
            __pipeline_memcpy_async(dAh + so, g_c1h + ga, 16);
            __pipeline_memcpy_async(dAl + so, g_c1l + ga, 16);
            __pipeline_memcpy_async(dWh + so, g_Wmh + gw, 16);
            __pipeline_memcpy_async(dWl + so, g_Wml + gw, 16);
        }
        __pipeline_commit();
    };

    pre(0);
    pre(1);
    for (int c = 0; c < 16; c++) {
        if (c + 1 < 16) __pipeline_wait_prior(1);
        else __pipeline_wait_prior(0);
        __syncthreads();
        if (c + 2 < 16) pre(c + 2);
        const int s = c % 3;
        bf* cAh = base + (s*4 + 0)*MB;
        bf* cAl = base + (s*4 + 1)*MB;
        bf* cWh = base + (s*4 + 2)*MB;
        bf* cWl = base + (s*4 + 3)*MB;
        for (int ks = 0; ks < 4; ks++) {
            wmma::fragment<wmma::matrix_a, 16, 16, 16, bf, wmma::row_major> fah;
            wmma::fragment<wmma::matrix_a, 16, 16, 16, bf, wmma::row_major> fal;
            wmma::load_matrix_sync(fah, cAh + (wr*16)*PA + ks*16, PA);
            wmma::load_matrix_sync(fal, cAl + (wr*16)*PA + ks*16, PA);
            wmma::fragment<wmma::matrix_b, 16, 16, 16, bf, wmma::col_major> fwh;
            wmma::fragment<wmma::matrix_b, 16, 16, 16, bf, wmma::col_major> fwl;
            const bf* ph = cWh + (wc*16)*PA + ks*16;
            const bf* pl = cWl + (wc*16)*PA + ks*16;
            wmma::load_matrix_sync(fwh, ph, PA);
            wmma::load_matrix_sync(fwl, pl, PA);
            wmma::mma_sync(acc, fah, fwh, acc);
            wmma::mma_sync(acc, fal, fwh, acc);
            wmma::mma_sync(acc, fah, fwl, acc);
        }
    }
    __syncthreads();

    {
        float* po = sout + (wr*16)*68 + wc*16;
        wmma::store_matrix_sync(po, acc, 68, wmma::mem_row_major);
    }
    __syncthreads();

    for (int e = tid; e < 4096; e += NTHR) {
        int ml = e >> 6;
        int nl = e & 63;
        float v = sout[ml*68 + nl] + bm[n0 + nl];
        bf ha, hb;
        split_bf(v, ha, hb);
        size_t di = (size_t)(m0 + ml)*HH + n0 + nl;
        g_msh[di] = ha;
        g_msl[di] = hb;
    }
    __syncthreads();
}

__device__ void fin_phase(const float* __restrict__ bfin, float* outT,
                          int bid, char* smb) {
    float* cs = (float*)smb;
    float* sh = (float*)(smb + 16384);
    float* red = (float*)(smb + 18432);
    const int b0 = bid*4;
    const int tid = threadIdx.x;
    for (int idx = tid; idx < 4*HH; idx += NTHR) {
        int rr = idx >> 10;
        int kk = idx & 1023;
        cs[idx] = __ldcg(&g_c2[(size_t)(b0 + rr)*HH + kk]);
    }
    __syncthreads();
    const int v = tid & 127;
    const int rh = tid >> 7;
    float a0 = 0.f;
    for (int k = 0; k < HH; k += 4) {
        float w0 = g_WfinT[(k + 0)*128 + v];
        float w1 = g_WfinT[(k + 1)*128 + v];
        float w2 = g_WfinT[(k + 2)*128 + v];
        float w3 = g_WfinT[(k + 3)*128 + v];
        float4 c0 = *(const float4*)(cs + rh*1024 + k);
        a0 += c0.x*w0 + c0.y*w1 + c0.z*w2 + c0.w*w3;
    }
    float bb = (v < VV) ? bfin[v] : 0.f;
    float v0 = (v < VV) ? (a0 + bb) : -1e30f;
    sh[rh*128 + v] = v0;
    __syncthreads();
    if (tid < 4) {
        float mx = -1e30f;
        for (int j = 0; j < VV; j++) mx = fmaxf(mx, sh[tid*128 + j]);
        float s = 0.f;
        for (int j = 0; j < VV; j++) s += expf(sh[tid*128 + j] - mx);
        red[tid] = mx;
        red[4 + tid] = logf(s);
    }
    __syncthreads();
    if (v < VV) {
        outT[(size_t)(b0 + rh)*VV + v] = v0 - red[rh] - red[4 + rh];
    }
    __syncthreads();
}

__global__ void __launch_bounds__(NTHR)
lstm_tc(const float* __restrict__ bm, const float* __restrict__ bfin,
        float* __restrict__ out) {
    extern __shared__ char smb[];
    const int bid = blockIdx.x;
    unsigned expected = 0;
    const int mt = bid >> 5;
    const int nt = bid & 31;

    for (int t = 0; t < TT; t++) {
        const int cur = t & 1;
        const int nxt = cur ^ 1;
        big_phase(g_h1h[cur], g_h1l[cur], HH, 16,
                  g_xh + (long)t*BB*128, g_xl + (long)t*BB*128, 128,
                  g_W1h, g_W1l, K1P, 18,
                  g_bias1, g_c1, g_h1h[nxt], g_h1l[nxt],
                  g_c1h, g_c1l, mt, nt, smb);
        gsync(expected);
        mid_phase(bm, bid, smb);
        gsync(expected);
        big_phase(g_msh, g_msl, HH, 16,
                  g_h2h[cur], g_h2l[cur], HH,
                  g_W2h, g_W2l, K2P, 32,
                  g_bias2, g_c2, g_h2h[nxt], g_h2l[nxt],
                  (bf*)0, (bf*)0, mt, nt, smb);
        gsync(expected);
        fin_phase(bfin, out + (size_t)t*BB*VV, bid, smb);
    }
}

extern "C" void kernel_launch(void* const* d_in, const int* in_sizes,
                              int n_in, void* d_out, int out_size) {
    const float* x = (const float*)d_in[0];
    const float* Wi1 = (const float*)d_in[1];
    const float* Wh1 = (const float*)d_in[2];
    const float* bi1 = (const float*)d_in[3];
    const float* bh1 = (const float*)d_in[4];
    const float* Wm = (const float*)d_in[5];
    const float* bm = (const float*)d_in[6];
    const float* Wi2 = (const float*)d_in[7];
    const float* Wh2 = (const float*)d_in[8];
    const float* bi2 = (const float*)d_in[9];
    const float* bh2 = (const float*)d_in[10];
    const float* Wf = (const float*)d_in[11];
    const float* bfin = (const float*)d_in[12];
    float* out = (float*)d_out;

    cudaFuncSetAttribute(lstm_tc,
                         cudaFuncAttributeMaxDynamicSharedMemorySize, DSM);
    prep<<<4096, 256>>>(x, Wi1, Wh1, bi1, bh1, Wm,
                        Wi2, Wh2, bi2, bh2, Wf);
    lstm_tc<<<NB, NTHR, DSM>>>(bm, bfin, out);
}

// round 16
// speedup vs baseline: 1.3671x; 1.3413x over previous
#include <cuda_runtime.h>
#include <cuda_bf16.h>
#include <cuda_pipeline.h>
#include <mma.h>
#include <math.h>

using namespace nvcuda;

constexpr int TT = 180;
constexpr int BB = 512;
constexpr int II = 108;
constexpr int HH = 1024;
constexpr int VV = 108;
constexpr int G4 = 4096;
constexpr int NB = 128;
constexpr int NTHR = 512;
constexpr int K1P = 1152;
constexpr int K2P = 2048;
constexpr int PA = 72;
constexpr int PO = 132;
constexpr int BUF = 128*PA;
constexpr int DSM = 3*3*BUF*2;

typedef __nv_bfloat16 bf;

__device__ bf g_W1h[(long)G4*K1P];
__device__ bf g_W2h[(long)G4*K2P];
__device__ bf g_Wmh[(long)HH*HH];
__device__ bf g_xh[(long)TT*BB*128], g_xl[(long)TT*BB*128];
__device__ bf g_h1h[2][BB*HH], g_h1l[2][BB*HH];
__device__ bf g_h2h[2][BB*HH], g_h2l[2][BB*HH];
__device__ bf g_c1h[BB*HH], g_c1l[BB*HH];
__device__ bf g_msh[BB*HH], g_msl[BB*HH];
__device__ float g_c1[BB*HH], g_c2[BB*HH];
__device__ float g_bias1[G4], g_bias2[G4];
__device__ float g_WfinT[HH*128];
__device__ unsigned g_arrive;
__device__ volatile unsigned g_release;

__device__ __forceinline__ void split_bf(float v, bf& hi, bf& lo) {
    hi = __float2bfloat16(v);
    lo = __float2bfloat16(v - __bfloat162float(hi));
}

__device__ __forceinline__ float sigmf(float x) {
    return 1.f / (1.f + expf(-x));
}

__device__ __forceinline__ int prow_n(int p) {
    return ((p >> 5) & 3)*HH + (p >> 7)*32 + (p & 31);
}

__global__ void prep(const float* __restrict__ x,
                     const float* __restrict__ Wi1,
                     const float* __restrict__ Wh1,
                     const float* __restrict__ bi1,
                     const float* __restrict__ bh1,
                     const float* __restrict__ Wm,
                     const float* __restrict__ Wi2,
                     const float* __restrict__ Wh2,
                     const float* __restrict__ bi2,
                     const float* __restrict__ bh2,
                     const float* __restrict__ Wf) {
    if (blockIdx.x == 0 && threadIdx.x == 0) {
        g_arrive = 0u;
        g_release = 0u;
    }
    const long NW1 = (long)G4*K1P;
    const long NW2 = (long)G4*K2P;
    const long NWM = (long)HH*HH;
    const long NX = (long)TT*BB*128;
    const long NH = (long)BB*HH;
    const long total = NW1 + NW2 + NWM + NX + 6*NH + 2*G4 + (long)HH*128;
    long idx = blockIdx.x*(long)blockDim.x + threadIdx.x;
    const long stride = (long)gridDim.x*blockDim.x;
    for (; idx < total; idx += stride) {
        long i = idx;
        if (i < NW1) {
            int p = (int)(i / K1P);
            int k = (int)(i - (long)p*K1P);
            int n = prow_n(p);
            float v = 0.f;
            if (k < HH) v = Wh1[(long)n*HH + k];
            else if (k - HH < II) v = Wi1[(long)n*II + (k - HH)];
            g_W1h[i] = __float2bfloat16(v);
            continue;
        }
        i -= NW1;
        if (i < NW2) {
            int p = (int)(i >> 11);
            int k = (int)(i & 2047);
            int n = prow_n(p);
            float v;
            if (k < HH) v = Wi2[(long)n*HH + k];
            else v = Wh2[(long)n*HH + (k - HH)];
            g_W2h[i] = __float2bfloat16(v);
            continue;
        }
        i -= NW2;
        if (i < NWM) {
            g_Wmh[i] = __float2bfloat16(Wm[i]);
            continue;
        }
        i -= NWM;
        if (i < NX) {
            int t = (int)(i / (BB*128));
            int r = (int)(i - (long)t*BB*128);
            int b = r >> 7;
            int kx = r & 127;
            float v = 0.f;
            if (kx < II) v = x[((long)t*BB + b)*II + kx];
            bf hi, lo;
            split_bf(v, hi, lo);
            g_xh[i] = hi;
            g_xl[i] = lo;
            continue;
        }
        i -= NX;
        if (i < 4*NH) {
            long a = i / NH;
            long off = i - a*NH;
            bf z = __float2bfloat16(0.f);
            if (a == 0) g_h1h[0][off] = z;
            else if (a == 1) g_h1l[0][off] = z;
            else if (a == 2) g_h2h[0][off] = z;
            else g_h2l[0][off] = z;
            continue;
        }
        i -= 4*NH;
        if (i < NH) { g_c1[i] = 0.f; continue; }
        i -= NH;
        if (i < NH) { g_c2[i] = 0.f; continue; }
        i -= NH;
        if (i < G4) {
            int n = prow_n((int)i);
            g_bias1[i] = bi1[n] + bh1[n];
            continue;
        }
        i -= G4;
        if (i < G4) {
            int n = prow_n((int)i);
            g_bias2[i] = bi2[n] + bh2[n];
            continue;
        }
        i -= G4;
        int k = (int)(i >> 7);
        int v = (int)(i & 127);
        g_WfinT[i] = (v < VV) ? Wf[(long)v*HH + k] : 0.f;
    }
}

__device__ __forceinline__ void gsync(unsigned& expected) {
    __syncthreads();
    if (threadIdx.x == 0) {
        __threadfence();
        expected += NB;
        unsigned a = atomicAdd(&g_arrive, 1u) + 1u;
        if (a == expected) g_release = expected;
        else while (g_release < expected) { __nanosleep(64); }
        __threadfence();
    }
    __syncthreads();
}

__device__ void big_phase(const bf* a1h, const bf* a1l, int a1w, int a1c,
                          const bf* a2h, const bf* a2l, int a2w,
                          const bf* wHi, int kW, int nch,
                          const float* biasP, float* cst,
                          bf* hOh, bf* hOl, bf* cOh, bf* cOl,
                          int mt, int nt, char* smb) {
    bf* base = (bf*)smb;
    float* sout = (float*)smb;
    const int tid = threadIdx.x;
    const int wid = tid >> 5;
    const int wr = wid & 3;
    const int wc = wid >> 2;
    const int m0 = mt*128;
    const int n0 = nt*128;

    wmma::fragment<wmma::accumulator, 16, 16, 16, float> acc[2][2];
    for (int i = 0; i < 2; i++)
        for (int j = 0; j < 2; j++)
            wmma::fill_fragment(acc[i][j], 0.f);

    auto pre = [&](int c) {
        const int s = c % 3;
        const bf* ah;
        const bf* al;
        int aw, col;
        if (c < a1c) {
            ah = a1h; al = a1l; aw = a1w; col = c*64;
        } else {
            ah = a2h; al = a2l; aw = a2w; col = (c - a1c)*64;
        }
        bf* dAh = base + (s*3 + 0)*BUF;
        bf* dAl = base + (s*3 + 1)*BUF;
        bf* dWh = base + (s*3 + 2)*BUF;
        for (int i = tid; i < 1024; i += NTHR) {
            int r = i >> 3;
            int cg = (i & 7)*8;
            int so = r*PA + cg;
            __pipeline_memcpy_async(dAh + so, ah + (size_t)(m0 + r)*aw + col + cg, 16);
            __pipeline_memcpy_async(dAl + so, al + (size_t)(m0 + r)*aw + col + cg, 16);
            __pipeline_memcpy_async(dWh + so, wHi + (size_t)(n0 + r)*kW + c*64 + cg, 16);
        }
        __pipeline_commit();
    };

    pre(0);
    pre(1);
    for (int c = 0; c < nch; c++) {
        if (c + 1 < nch) __pipeline_wait_prior(1);
        else __pipeline_wait_prior(0);
        __syncthreads();
        if (c + 2 < nch) pre(c + 2);
        const int s = c % 3;
        bf* cAh = base + (s*3 + 0)*BUF;
        bf* cAl = base + (s*3 + 1)*BUF;
        bf* cWh = base + (s*3 + 2)*BUF;
        for (int ks = 0; ks < 4; ks++) {
            wmma::fragment<wmma::matrix_a, 16, 16, 16, bf, wmma::row_major> fah[2];
            wmma::fragment<wmma::matrix_a, 16, 16, 16, bf, wmma::row_major> fal[2];
            for (int i = 0; i < 2; i++) {
                const bf* pa = cAh + (wr*32 + i*16)*PA + ks*16;
                const bf* pb = cAl + (wr*32 + i*16)*PA + ks*16;
                wmma::load_matrix_sync(fah[i], pa, PA);
                wmma::load_matrix_sync(fal[i], pb, PA);
            }
            for (int j = 0; j < 2; j++) {
                wmma::fragment<wmma::matrix_b, 16, 16, 16, bf, wmma::col_major> fwh;
                const bf* ph = cWh + (wc*32 + j*16)*PA + ks*16;
                wmma::load_matrix_sync(fwh, ph, PA);
                for (int i = 0; i < 2; i++) {
                    wmma::mma_sync(acc[i][j], fah[i], fwh, acc[i][j]);
                    wmma::mma_sync(acc[i][j], fal[i], fwh, acc[i][j]);
                }
            }
        }
    }
    __syncthreads();

    for (int i = 0; i < 2; i++)
        for (int j = 0; j < 2; j++) {
            float* po = sout + (wr*32 + i*16)*PO + wc*32 + j*16;
            wmma::store_matrix_sync(po, acc[i][j], PO, wmma::mem_row_major);
        }
    __syncthreads();

    for (int e = tid; e < 4096; e += NTHR) {
        int ml = e >> 5;
        int jin = e & 31;
        const float* bse = sout + ml*PO + jin;
        float ig = sigmf(bse[0] + biasP[n0 + jin]);
        float fg = sigmf(bse[32] + biasP[n0 + 32 + jin]);
        float gg = tanhf(bse[64] + biasP[n0 + 64 + jin]);
        float og = sigmf(bse[96] + biasP[n0 + 96 + jin]);
        int j = nt*32 + jin;
        size_t ci = (size_t)(m0 + ml)*HH + j;
        float cn = fg*cst[ci] + ig*gg;
        cst[ci] = cn;
        float hn = og*tanhf(cn);
        bf ha, hb;
        split_bf(hn, ha, hb);
        hOh[ci] = ha;
        hOl[ci] = hb;
        if (cOh != 0) {
            bf ca, cb;
            split_bf(cn, ca, cb);
            cOh[ci] = ca;
            cOl[ci] = cb;
        }
    }
    __syncthreads();
}

__device__ void mid_phase(const float* bm, int bid, char* smb) {
    bf* base = (bf*)smb;
    float* sout = (float*)smb;
    const int tid = threadIdx.x;
    const int wid = tid >> 5;
    const int wr = wid & 3;
    const int wc = wid >> 2;
    const int m0 = (bid >> 4)*64;
    const int n0 = (bid & 15)*64;
    const int MB = 64*PA;

    wmma::fragment<wmma::accumulator, 16, 16, 16, float> acc;
    wmma::fill_fragment(acc, 0.f);

    auto pre = [&](int c) {
        const int s = c % 3;
        bf* dAh = base + (s*3 + 0)*MB;
        bf* dAl = base + (s*3 + 1)*MB;
        bf* dWh = base + (s*3 + 2)*MB;
        for (int i = tid; i < 512; i += NTHR) {
            int r = i >> 3;
            int cg = (i & 7)*8;
            int so = r*PA + cg;
            size_t ga = (size_t)(m0 + r)*HH + c*64 + cg;
            size_t gw = (size_t)(n0 + r)*HH + c*64 + cg;
            __pipeline_memcpy_async(dAh + so, g_c1h + ga, 16);
            __pipeline_memcpy_async(dAl + so, g_c1l + ga, 16);
            __pipeline_memcpy_async(dWh + so, g_Wmh + gw, 16);
        }
        __pipeline_commit();
    };

    pre(0);
    pre(1);
    for (int c = 0; c < 16; c++) {
        if (c + 1 < 16) __pipeline_wait_prior(1);
        else __pipeline_wait_prior(0);
        __syncthreads();
        if (c + 2 < 16) pre(c + 2);
        const int s = c % 3;
        bf* cAh = base + (s*3 + 0)*MB;
        bf* cAl = base + (s*3 + 1)*MB;
        bf* cWh = base + (s*3 + 2)*MB;
        for (int ks = 0; ks < 4; ks++) {
            wmma::fragment<wmma::matrix_a, 16, 16, 16, bf, wmma::row_major> fah;
            wmma::fragment<wmma::matrix_a, 16, 16, 16, bf, wmma::row_major> fal;
            wmma::load_matrix_sync(fah, cAh + (wr*16)*PA + ks*16, PA);
            wmma::load_matrix_sync(fal, cAl + (wr*16)*PA + ks*16, PA);
            wmma::fragment<wmma::matrix_b, 16, 16, 16, bf, wmma::col_major> fwh;
            const bf* ph = cWh + (wc*16)*PA + ks*16;
            wmma::load_matrix_sync(fwh, ph, PA);
            wmma::mma_sync(acc, fah, fwh, acc);
            wmma::mma_sync(acc, fal, fwh, acc);
        }
    }
    __syncthreads();

    {
        float* po = sout + (wr*16)*68 + wc*16;
        wmma::store_matrix_sync(po, acc, 68, wmma::mem_row_major);
    }
    __syncthreads();

    for (int e = tid; e < 4096; e += NTHR) {
        int ml = e >> 6;
        int nl = e & 63;
        float v = sout[ml*68 + nl] + bm[n0 + nl];
        bf ha, hb;
        split_bf(v, ha, hb);
        size_t di = (size_t)(m0 + ml)*HH + n0 + nl;
        g_msh[di] = ha;
        g_msl[di] = hb;
    }
    __syncthreads();
}

__device__ void fin_phase(const float* __restrict__ bfin, float* outT,
                          int bid, char* smb) {
    float* cs = (float*)smb;
    float* sh = (float*)(smb + 16384);
    float* red = (float*)(smb + 18432);
    const int b0 = bid*4;
    const int tid = threadIdx.x;
    for (int idx = tid; idx < 4*HH; idx += NTHR) {
        int rr = idx >> 10;
        int kk = idx & 1023;
        cs[idx] = __ldcg(&g_c2[(size_t)(b0 + rr)*HH + kk]);
    }
    __syncthreads();
    const int v = tid & 127;
    const int rh = tid >> 7;
    float a0 = 0.f;
    for (int k = 0; k < HH; k += 4) {
        float w0 = g_WfinT[(k + 0)*128 + v];
        float w1 = g_WfinT[(k + 1)*128 + v];
        float w2 = g_WfinT[(k + 2)*128 + v];
        float w3 = g_WfinT[(k + 3)*128 + v];
        float4 c0 = *(const float4*)(cs + rh*1024 + k);
        a0 += c0.x*w0 + c0.y*w1 + c0.z*w2 + c0.w*w3;
    }
    float bb = (v < VV) ? bfin[v] : 0.f;
    float v0 = (v < VV) ? (a0 + bb) : -1e30f;
    sh[rh*128 + v] = v0;
    __syncthreads();
    if (tid < 4) {
        float mx = -1e30f;
        for (int j = 0; j < VV; j++) mx = fmaxf(mx, sh[tid*128 + j]);
        float s = 0.f;
        for (int j = 0; j < VV; j++) s += expf(sh[tid*128 + j] - mx);
        red[tid] = mx;
        red[4 + tid] = logf(s);
    }
    __syncthreads();
    if (v < VV) {
        outT[(size_t)(b0 + rh)*VV + v] = v0 - red[rh] - red[4 + rh];
    }
    __syncthreads();
}

__global__ void __launch_bounds__(NTHR)
lstm_tc(const float* __restrict__ bm, const float* __restrict__ bfin,
        float* __restrict__ out) {
    extern __shared__ char smb[];
    const int bid = blockIdx.x;
    unsigned expected = 0;
    const int mt = bid >> 5;
    const int nt = bid & 31;

    for (int t = 0; t < TT; t++) {
        const int cur = t & 1;
        const int nxt = cur ^ 1;
        big_phase(g_h1h[cur], g_h1l[cur], HH, 16,
                  g_xh + (long)t*BB*128, g_xl + (long)t*BB*128, 128,
                  g_W1h, K1P, 18,
                  g_bias1, g_c1, g_h1h[nxt], g_h1l[nxt],
                  g_c1h, g_c1l, mt, nt, smb);
        gsync(expected);
        mid_phase(bm, bid, smb);
        gsync(expected);
        big_phase(g_msh, g_msl, HH, 16,
                  g_h2h[cur], g_h2l[cur], HH,
                  g_W2h, K2P, 32,
                  g_bias2, g_c2, g_h2h[nxt], g_h2l[nxt],
                  (bf*)0, (bf*)0, mt, nt, smb);
        gsync(expected);
        fin_phase(bfin, out + (size_t)t*BB*VV, bid, smb);
    }
}

extern "C" void kernel_launch(void* const* d_in, const int* in_sizes,
                              int n_in, void* d_out, int out_size) {
    const float* x = (const float*)d_in[0];
    const float* Wi1 = (const float*)d_in[1];
    const float* Wh1 = (const float*)d_in[2];
    const float* bi1 = (const float*)d_in[3];
    const float* bh1 = (const float*)d_in[4];
    const float* Wm = (const float*)d_in[5];
    const float* bm = (const float*)d_in[6];
    const float* Wi2 = (const float*)d_in[7];
    const float* Wh2 = (const float*)d_in[8];
    const float* bi2 = (const float*)d_in[9];
    const float* bh2 = (const float*)d_in[10];
    const float* Wf = (const float*)d_in[11];
    const float* bfin = (const float*)d_in[12];
    float* out = (float*)d_out;

    cudaFuncSetAttribute(lstm_tc,
                         cudaFuncAttributeMaxDynamicSharedMemorySize, DSM);
    prep<<<4096, 256>>>(x, Wi1, Wh1, bi1, bh1, Wm,
                        Wi2, Wh2, bi2, bh2, Wf);
    lstm_tc<<<NB, NTHR, DSM>>>(bm, bfin, out);
}

// round 17
// speedup vs baseline: 1.9684x; 1.4398x over previous
#include <cuda_runtime.h>
#include <cuda_bf16.h>
#include <cuda_pipeline.h>
#include <mma.h>
#include <math.h>

using namespace nvcuda;

constexpr int TT = 180;
constexpr int BB = 512;
constexpr int II = 108;
constexpr int HH = 1024;
constexpr int VV = 108;
constexpr int G4 = 4096;
constexpr int NB = 128;
constexpr int NTHR = 512;
constexpr int K1P = 1152;
constexpr int K2P = 2048;
constexpr int PA = 72;
constexpr int PO = 132;
constexpr int BUF = 128*PA;
constexpr int DSM = 3*2*BUF*2;

typedef __nv_bfloat16 bf;

__device__ bf g_W1h[(long)G4*K1P];
__device__ bf g_W2h[(long)G4*K2P];
__device__ bf g_Wmh[(long)HH*HH];
__device__ bf g_xh[(long)TT*BB*128];
__device__ bf g_h1h[2][BB*HH];
__device__ bf g_h2h[2][BB*HH];
__device__ bf g_c1h[BB*HH];
__device__ bf g_msh[BB*HH];
__device__ float g_c1[BB*HH], g_c2[BB*HH];
__device__ float g_bias1[G4], g_bias2[G4];
__device__ float g_WfinT[HH*128];
__device__ unsigned g_arrive;
__device__ volatile unsigned g_release;

__device__ __forceinline__ float sigmf(float x) {
    return 1.f / (1.f + expf(-x));
}

__device__ __forceinline__ int prow_n(int p) {
    return ((p >> 5) & 3)*HH + (p >> 7)*32 + (p & 31);
}

__global__ void prep(const float* __restrict__ x,
                     const float* __restrict__ Wi1,
                     const float* __restrict__ Wh1,
                     const float* __restrict__ bi1,
                     const float* __restrict__ bh1,
                     const float* __restrict__ Wm,
                     const float* __restrict__ Wi2,
                     const float* __restrict__ Wh2,
                     const float* __restrict__ bi2,
                     const float* __restrict__ bh2,
                     const float* __restrict__ Wf) {
    if (blockIdx.x == 0 && threadIdx.x == 0) {
        g_arrive = 0u;
        g_release = 0u;
    }
    const long NW1 = (long)G4*K1P;
    const long NW2 = (long)G4*K2P;
    const long NWM = (long)HH*HH;
    const long NX = (long)TT*BB*128;
    const long NH = (long)BB*HH;
    const long total = NW1 + NW2 + NWM + NX + 4*NH + 2*G4 + (long)HH*128;
    long idx = blockIdx.x*(long)blockDim.x + threadIdx.x;
    const long stride = (long)gridDim.x*blockDim.x;
    for (; idx < total; idx += stride) {
        long i = idx;
        if (i < NW1) {
            int p = (int)(i / K1P);
            int k = (int)(i - (long)p*K1P);
            int n = prow_n(p);
            float v = 0.f;
            if (k < HH) v = Wh1[(long)n*HH + k];
            else if (k - HH < II) v = Wi1[(long)n*II + (k - HH)];
            g_W1h[i] = __float2bfloat16(v);
            continue;
        }
        i -= NW1;
        if (i < NW2) {
            int p = (int)(i >> 11);
            int k = (int)(i & 2047);
            int n = prow_n(p);
            float v;
            if (k < HH) v = Wi2[(long)n*HH + k];
            else v = Wh2[(long)n*HH + (k - HH)];
            g_W2h[i] = __float2bfloat16(v);
            continue;
        }
        i -= NW2;
        if (i < NWM) {
            g_Wmh[i] = __float2bfloat16(Wm[i]);
            continue;
        }
        i -= NWM;
        if (i < NX) {
            int t = (int)(i / (BB*128));
            int r = (int)(i - (long)t*BB*128);
            int b = r >> 7;
            int kx = r & 127;
            float v = 0.f;
            if (kx < II) v = x[((long)t*BB + b)*II + kx];
            g_xh[i] = __float2bfloat16(v);
            continue;
        }
        i -= NX;
        if (i < 2*NH) {
            long a = i / NH;
            long off = i - a*NH;
            bf z = __float2bfloat16(0.f);
            if (a == 0) g_h1h[0][off] = z;
            else g_h2h[0][off] = z;
            continue;
        }
        i -= 2*NH;
        if (i < NH) { g_c1[i] = 0.f; continue; }
        i -= NH;
        if (i < NH) { g_c2[i] = 0.f; continue; }
        i -= NH;
        if (i < G4) {
            int n = prow_n((int)i);
            g_bias1[i] = bi1[n] + bh1[n];
            continue;
        }
        i -= G4;
        if (i < G4) {
            int n = prow_n((int)i);
            g_bias2[i] = bi2[n] + bh2[n];
            continue;
        }
        i -= G4;
        int k = (int)(i >> 7);
        int v = (int)(i & 127);
        g_WfinT[i] = (v < VV) ? Wf[(long)v*HH + k] : 0.f;
    }
}

__device__ __forceinline__ void gsync(unsigned& expected) {
    __syncthreads();
    if (threadIdx.x == 0) {
        __threadfence();
        expected += NB;
        unsigned a = atomicAdd(&g_arrive, 1u) + 1u;
        if (a == expected) g_release = expected;
        else while (g_release < expected) { __nanosleep(64); }
        __threadfence();
    }
    __syncthreads();
}

__device__ void big_phase(const bf* a1h, int a1w, int a1c,
                          const bf* a2h, int a2w,
                          const bf* wHi, int kW, int nch,
                          const float* biasP, float* cst,
                          bf* hOh, bf* cOh,
                          int mt, int nt, char* smb) {
    bf* base = (bf*)smb;
    float* sout = (float*)smb;
    const int tid = threadIdx.x;
    const int wid = tid >> 5;
    const int wr = wid & 3;
    const int wc = wid >> 2;
    const int m0 = mt*128;
    const int n0 = nt*128;

    wmma::fragment<wmma::accumulator, 16, 16, 16, float> acc[2][2];
    for (int i = 0; i < 2; i++)
        for (int j = 0; j < 2; j++)
            wmma::fill_fragment(acc[i][j], 0.f);

    auto pre = [&](int c) {
        const int s = c % 3;
        const bf* ah;
        int aw, col;
        if (c < a1c) {
            ah = a1h; aw = a1w; col = c*64;
        } else {
            ah = a2h; aw = a2w; col = (c - a1c)*64;
        }
        bf* dAh = base + (s*2 + 0)*BUF;
        bf* dWh = base + (s*2 + 1)*BUF;
        for (int i = tid; i < 1024; i += NTHR) {
            int r = i >> 3;
            int cg = (i & 7)*8;
            int so = r*PA + cg;
            __pipeline_memcpy_async(dAh + so, ah + (size_t)(m0 + r)*aw + col + cg, 16);
            __pipeline_memcpy_async(dWh + so, wHi + (size_t)(n0 + r)*kW + c*64 + cg, 16);
        }
        __pipeline_commit();
    };

    pre(0);
    pre(1);
    for (int c = 0; c < nch; c++) {
        if (c + 1 < nch) __pipeline_wait_prior(1);
        else __pipeline_wait_prior(0);
        __syncthreads();
        if (c + 2 < nch) pre(c + 2);
        const int s = c % 3;
        bf* cAh = base + (s*2 + 0)*BUF;
        bf* cWh = base + (s*2 + 1)*BUF;
        for (int ks = 0; ks < 4; ks++) {
            wmma::fragment<wmma::matrix_a, 16, 16, 16, bf, wmma::row_major> fah[2];
            for (int i = 0; i < 2; i++) {
                const bf* pa = cAh + (wr*32 + i*16)*PA + ks*16;
                wmma::load_matrix_sync(fah[i], pa, PA);
            }
            for (int j = 0; j < 2; j++) {
                wmma::fragment<wmma::matrix_b, 16, 16, 16, bf, wmma::col_major> fwh;
                const bf* ph = cWh + (wc*32 + j*16)*PA + ks*16;
                wmma::load_matrix_sync(fwh, ph, PA);
                for (int i = 0; i < 2; i++) {
                    wmma::mma_sync(acc[i][j], fah[i], fwh, acc[i][j]);
                }
            }
        }
    }
    __syncthreads();

    for (int i = 0; i < 2; i++)
        for (int j = 0; j < 2; j++) {
            float* po = sout + (wr*32 + i*16)*PO + wc*32 + j*16;
            wmma::store_matrix_sync(po, acc[i][j], PO, wmma::mem_row_major);
        }
    __syncthreads();

    for (int e = tid; e < 4096; e += NTHR) {
        int ml = e >> 5;
        int jin = e & 31;
        const float* bse = sout + ml*PO + jin;
        float ig = sigmf(bse[0] + biasP[n0 + jin]);
        float fg = sigmf(bse[32] + biasP[n0 + 32 + jin]);
        float gg = tanhf(bse[64] + biasP[n0 + 64 + jin]);
        float og = sigmf(bse[96] + biasP[n0 + 96 + jin]);
        int j = nt*32 + jin;
        size_t ci = (size_t)(m0 + ml)*HH + j;
        float cn = fg*cst[ci] + ig*gg;
        cst[ci] = cn;
        float hn = og*tanhf(cn);
        hOh[ci] = __float2bfloat16(hn);
        if (cOh != 0) {
            cOh[ci] = __float2bfloat16(cn);
        }
    }
    __syncthreads();
}

__device__ void mid_phase(const float* bm, int bid, char* smb) {
    bf* base = (bf*)smb;
    float* sout = (float*)smb;
    const int tid = threadIdx.x;
    const int wid = tid >> 5;
    const int wr = wid & 3;
    const int wc = wid >> 2;
    const int m0 = (bid >> 4)*64;
    const int n0 = (bid & 15)*64;
    const int MB = 64*PA;

    wmma::fragment<wmma::accumulator, 16, 16, 16, float> acc;
    wmma::fill_fragment(acc, 0.f);

    auto pre = [&](int c) {
        const int s = c % 3;
        bf* dAh = base + (s*2 + 0)*MB;
        bf* dWh = base + (s*2 + 1)*MB;
        for (int i = tid; i < 512; i += NTHR) {
            int r = i >> 3;
            int cg = (i & 7)*8;
            int so = r*PA + cg;
            size_t ga = (size_t)(m0 + r)*HH + c*64 + cg;
            size_t gw = (size_t)(n0 + r)*HH + c*64 + cg;
            __pipeline_memcpy_async(dAh + so, g_c1h + ga, 16);
            __pipeline_memcpy_async(dWh + so, g_Wmh + gw, 16);
        }
        __pipeline_commit();
    };

    pre(0);
    pre(1);
    for (int c = 0; c < 16; c++) {
        if (c + 1 < 16) __pipeline_wait_prior(1);
        else __pipeline_wait_prior(0);
        __syncthreads();
        if (c + 2 < 16) pre(c + 2);
        const int s = c % 3;
        bf* cAh = base + (s*2 + 0)*MB;
        bf* cWh = base + (s*2 + 1)*MB;
        for (int ks = 0; ks < 4; ks++) {
            wmma::fragment<wmma::matrix_a, 16, 16, 16, bf, wmma::row_major> fah;
            wmma::load_matrix_sync(fah, cAh + (wr*16)*PA + ks*16, PA);
            wmma::fragment<wmma::matrix_b, 16, 16, 16, bf, wmma::col_major> fwh;
            const bf* ph = cWh + (wc*16)*PA + ks*16;
            wmma::load_matrix_sync(fwh, ph, PA);
            wmma::mma_sync(acc, fah, fwh, acc);
        }
    }
    __syncthreads();

    {
        float* po = sout + (wr*16)*68 + wc*16;
        wmma::store_matrix_sync(po, acc, 68, wmma::mem_row_major);
    }
    __syncthreads();

    for (int e = tid; e < 4096; e += NTHR) {
        int ml = e >> 6;
        int nl = e & 63;
        float v = sout[ml*68 + nl] + bm[n0 + nl];
        size_t di = (size_t)(m0 + ml)*HH + n0 + nl;
        g_msh[di] = __float2bfloat16(v);
    }
    __syncthreads();
}

__device__ void fin_phase(const float* __restrict__ bfin, float* outT,
                          int bid, char* smb) {
    float* cs = (float*)smb;
    float* sh = (float*)(smb + 16384);
    float* red = (float*)(smb + 18432);
    const int b0 = bid*4;
    const int tid = threadIdx.x;
    for (int idx = tid; idx < 4*HH; idx += NTHR) {
        int rr = idx >> 10;
        int kk = idx & 1023;
        cs[idx] = __ldcg(&g_c2[(size_t)(b0 + rr)*HH + kk]);
    }
    __syncthreads();
    const int v = tid & 127;
    const int rh = tid >> 7;
    float a0 = 0.f;
    for (int k = 0; k < HH; k += 4) {
        float w0 = g_WfinT[(k + 0)*128 + v];
        float w1 = g_WfinT[(k + 1)*128 + v];
        float w2 = g_WfinT[(k + 2)*128 + v];
        float w3 = g_WfinT[(k + 3)*128 + v];
        float4 c0 = *(const float4*)(cs + rh*1024 + k);
        a0 += c0.x*w0 + c0.y*w1 + c0.z*w2 + c0.w*w3;
    }
    float bb = (v < VV) ? bfin[v] : 0.f;
    float v0 = (v < VV) ? (a0 + bb) : -1e30f;
    sh[rh*128 + v] = v0;
    __syncthreads();
    if (tid < 4) {
        float mx = -1e30f;
        for (int j = 0; j < VV; j++) mx = fmaxf(mx, sh[tid*128 + j]);
        float s = 0.f;
        for (int j = 0; j < VV; j++) s += expf(sh[tid*128 + j] - mx);
        red[tid] = mx;
        red[4 + tid] = logf(s);
    }
    __syncthreads();
    if (v < VV) {
        outT[(size_t)(b0 + rh)*VV + v] = v0 - red[rh] - red[4 + rh];
    }
    __syncthreads();
}

__global__ void __launch_bounds__(NTHR)
lstm_tc(const float* __restrict__ bm, const float* __restrict__ bfin,
        float* __restrict__ out) {
    extern __shared__ char smb[];
    const int bid = blockIdx.x;
    unsigned expected = 0;
    const int mt = bid >> 5;
    const int nt = bid & 31;

    for (int t = 0; t < TT; t++) {
        const int cur = t & 1;
        const int nxt = cur ^ 1;
        big_phase(g_h1h[cur], HH, 16,
                  g_xh + (long)t*BB*128, 128,
                  g_W1h, K1P, 18,
                  g_bias1, g_c1, g_h1h[nxt],
                  g_c1h, mt, nt, smb);
        gsync(expected);
        mid_phase(bm, bid, smb);
        gsync(expected);
        big_phase(g_msh, HH, 16,
                  g_h2h[cur], HH,
                  g_W2h, K2P, 32,
                  g_bias2, g_c2, g_h2h[nxt],
                  (bf*)0, mt, nt, smb);
        gsync(expected);
        fin_phase(bfin, out + (size_t)t*BB*VV, bid, smb);
    }
}

extern "C" void kernel_launch(void* const* d_in, const int* in_sizes,
                              int n_in, void* d_out, int out_size) {
    const float* x = (const float*)d_in[0];
    const float* Wi1 = (const float*)d_in[1];
    const float* Wh1 = (const float*)d_in[2];
    const float* bi1 = (const float*)d_in[3];
    const float* bh1 = (const float*)d_in[4];
    const float* Wm = (const float*)d_in[5];
    const float* bm = (const float*)d_in[6];
    const float* Wi2 = (const float*)d_in[7];
    const float* Wh2 = (const float*)d_in[8];
    const float* bi2 = (const float*)d_in[9];
    const float* bh2 = (const float*)d_in[10];
    const float* Wf = (const float*)d_in[11];
    const float* bfin = (const float*)d_in[12];
    float* out = (float*)d_out;

    cudaFuncSetAttribute(lstm_tc,
                         cudaFuncAttributeMaxDynamicSharedMemorySize, DSM);
    prep<<<4096, 256>>>(x, Wi1, Wh1, bi1, bh1, Wm,
                        Wi2, Wh2, bi2, bh2, Wf);
    lstm_tc<<<NB, NTHR, DSM>>>(bm, bfin, out);
}